// round 6
// baseline (speedup 1.0000x reference)
#include <cuda_runtime.h>
#include <cuda_bf16.h>
#include <cstdint>
#include <math.h>

#define NQ 8192
#define NK 8192
#define DIM 512
#define CSCALE 0.01f
// exp(-0.5*(qd+kd)+55) = 2^(-0.5*log2e*(qd+kd) + 55*log2e)
#define NEG_HALF_LOG2E (-0.72134752044448170f)
#define SHIFT_LOG2E    (79.34822724889299f)

// ---------------------------------------------------------------------------
// Scratch (static device arrays; no runtime allocation)
// ---------------------------------------------------------------------------
__device__ __nv_bfloat16 g_qh[NQ * DIM];
__device__ __nv_bfloat16 g_ql[NQ * DIM];
__device__ __nv_bfloat16 g_kh[NK * DIM];
__device__ __nv_bfloat16 g_kl[NK * DIM];
__device__ float g_qq[NQ];
__device__ float g_kk[NK];
__device__ float g_rsum[NQ];

// ---------------------------------------------------------------------------
// helpers
// ---------------------------------------------------------------------------
__device__ __forceinline__ uint32_t smem_u32(const void* p) {
    uint32_t a;
    asm("{ .reg .u64 t; cvta.to.shared.u64 t, %1; cvt.u32.u64 %0, t; }" : "=r"(a) : "l"(p));
    return a;
}

// SW64 swizzle for 64-byte rows: XOR bits[5:4] with bits[8:7]
#define SWZ64(off) ((off) ^ (((off) >> 3) & 0x30))

__device__ __forceinline__ void cp_async16(uint32_t dst, const void* src) {
    asm volatile("cp.async.cg.shared.global [%0], [%1], 16;" :: "r"(dst), "l"(src));
}

__device__ __forceinline__ void ldsm_x4(uint32_t& r0, uint32_t& r1, uint32_t& r2, uint32_t& r3,
                                        uint32_t addr) {
    asm volatile("ldmatrix.sync.aligned.m8n8.x4.shared.b16 {%0,%1,%2,%3}, [%4];"
                 : "=r"(r0), "=r"(r1), "=r"(r2), "=r"(r3) : "r"(addr));
}

__device__ __forceinline__ void mma16816(float* c, uint32_t a0, uint32_t a1, uint32_t a2,
                                         uint32_t a3, uint32_t b0, uint32_t b1) {
    asm volatile(
        "mma.sync.aligned.m16n8k16.row.col.f32.bf16.bf16.f32 "
        "{%0,%1,%2,%3}, {%4,%5,%6,%7}, {%8,%9}, {%0,%1,%2,%3};"
        : "+f"(c[0]), "+f"(c[1]), "+f"(c[2]), "+f"(c[3])
        : "r"(a0), "r"(a1), "r"(a2), "r"(a3), "r"(b0), "r"(b1));
}

__device__ __forceinline__ float fsqrt_approx(float x) {
    float r; asm("sqrt.approx.f32 %0, %1;" : "=f"(r) : "f"(x)); return r;
}
__device__ __forceinline__ float fexp2_approx(float x) {
    float r; asm("ex2.approx.f32 %0, %1;" : "=f"(r) : "f"(x)); return r;
}

// exp(score + 55) with fixed shift (softmax-invariant; scores always << 0)
__device__ __forceinline__ float score_exp(float qk, float qq, float kk) {
    float norm2 = fmaxf(qq + kk - 2.0f * qk, 0.0f);
    float qdot  = qq - qk;
    float kdot  = qk - kk;
    float qd = fsqrt_approx(fmaf(CSCALE * qdot, qdot, norm2));
    float kd = fsqrt_approx(fmaf(CSCALE * kdot, kdot, norm2));
    return fexp2_approx(fmaf(NEG_HALF_LOG2E, qd + kd, SHIFT_LOG2E));
}

// ---------------------------------------------------------------------------
// Kernel 1: per-row sumsq + bf16 hi/lo split. One warp per row. Zeroes g_rsum.
// ---------------------------------------------------------------------------
__global__ void __launch_bounds__(256)
prep_kernel(const float* __restrict__ Q, const float* __restrict__ Kp) {
    int gw   = (blockIdx.x * blockDim.x + threadIdx.x) >> 5;
    int lane = threadIdx.x & 31;
    bool isQ = gw < NQ;
    int row  = isQ ? gw : gw - NQ;
    const float4* src = reinterpret_cast<const float4*>((isQ ? Q : Kp) + (size_t)row * DIM);
    __nv_bfloat16* hi = isQ ? g_qh : g_kh;
    __nv_bfloat16* lo = isQ ? g_ql : g_kl;

    float s = 0.0f;
#pragma unroll
    for (int i = 0; i < DIM / 128; i++) {
        float4 v = src[i * 32 + lane];
        s = fmaf(v.x, v.x, s); s = fmaf(v.y, v.y, s);
        s = fmaf(v.z, v.z, s); s = fmaf(v.w, v.w, s);

        __nv_bfloat16 h0 = __float2bfloat16(v.x);
        __nv_bfloat16 h1 = __float2bfloat16(v.y);
        __nv_bfloat16 h2 = __float2bfloat16(v.z);
        __nv_bfloat16 h3 = __float2bfloat16(v.w);
        __nv_bfloat16 l0 = __float2bfloat16(v.x - __bfloat162float(h0));
        __nv_bfloat16 l1 = __float2bfloat16(v.y - __bfloat162float(h1));
        __nv_bfloat16 l2 = __float2bfloat16(v.z - __bfloat162float(h2));
        __nv_bfloat16 l3 = __float2bfloat16(v.w - __bfloat162float(h3));

        int col = (i * 32 + lane) * 4;
        __nv_bfloat162 h01 = __nv_bfloat162(h0, h1);
        __nv_bfloat162 h23 = __nv_bfloat162(h2, h3);
        __nv_bfloat162 l01 = __nv_bfloat162(l0, l1);
        __nv_bfloat162 l23 = __nv_bfloat162(l2, l3);
        uint2 hu = make_uint2(*reinterpret_cast<uint32_t*>(&h01), *reinterpret_cast<uint32_t*>(&h23));
        uint2 lu = make_uint2(*reinterpret_cast<uint32_t*>(&l01), *reinterpret_cast<uint32_t*>(&l23));
        *reinterpret_cast<uint2*>(hi + (size_t)row * DIM + col) = hu;
        *reinterpret_cast<uint2*>(lo + (size_t)row * DIM + col) = lu;
    }
#pragma unroll
    for (int off = 16; off; off >>= 1) s += __shfl_xor_sync(0xFFFFFFFFu, s, off);
    if (lane == 0) {
        if (isQ) { g_qq[row] = s; g_rsum[row] = 0.0f; }
        else     { g_kk[row] = s; }
    }
}

// ---------------------------------------------------------------------------
// Kernel 2: mma.sync bf16 split GEMM (K_eff=1536) + fused score/exp epilogue.
// CTA tile 128x256, 8 warps (2 x 4), warptile 64x64, K-chunk 32, double buffer.
// smem: A 2x8KB + B 2x16KB = 48KB static (exactly at the limit).
// ---------------------------------------------------------------------------
#define NCHUNK 48
#define CK 32
#define ABUF 8192    // 128 rows x 64 bytes
#define BBUF 16384   // 256 rows x 64 bytes

__global__ void __launch_bounds__(256, 1)
gemm_score_kernel(float* __restrict__ out) {
    __shared__ __align__(128) uint8_t sA[2 * ABUF];
    __shared__ __align__(128) uint8_t sB[2 * BBUF];

    const int tid  = threadIdx.x;
    const int wid  = tid >> 5;
    const int lane = tid & 31;
    const int bm = blockIdx.y;
    const int bn = blockIdx.x;
    const int warp_m = wid & 1;     // 0..1 -> 64-row half
    const int warp_n = wid >> 1;    // 0..3 -> 64-col quarter

    const uint32_t sa_base = smem_u32(sA);
    const uint32_t sb_base = smem_u32(sB);

    // --- precompute per-lane ldmatrix byte offsets (within a buffer) ---
    uint32_t offA[4][2], offB[4][2];
#pragma unroll
    for (int mt = 0; mt < 4; mt++) {
        int m = warp_m * 64 + mt * 16 + (lane & 15);
#pragma unroll
        for (int ks = 0; ks < 2; ks++) {
            int o = m * 64 + ks * 32 + (lane >> 4) * 16;
            offA[mt][ks] = SWZ64(o);
        }
    }
#pragma unroll
    for (int nt2 = 0; nt2 < 4; nt2++) {
        int n = warp_n * 64 + nt2 * 16 + (lane & 7) + ((lane >> 4) & 1) * 8;
#pragma unroll
        for (int ks = 0; ks < 2; ks++) {
            int o = n * 64 + ks * 32 + ((lane >> 3) & 1) * 16;
            offB[nt2][ks] = SWZ64(o);
        }
    }

    // loader mapping: A 2 threads/row x 2 segs; B 1 thread/row x 4 segs
    const int lrowA = tid >> 1;
    const int lsegA = (tid & 1) * 2;

    auto issue_chunk = [&](int c, int buf) {
        const __nv_bfloat16 *as, *bs;
        if (c < 16)      { as = g_qh; bs = g_kh; }
        else if (c < 32) { as = g_qh; bs = g_kl; }
        else             { as = g_ql; bs = g_kh; }
        int kc = (c & 15) * CK;
        const __nv_bfloat16* ag = as + (size_t)(bm * 128 + lrowA) * DIM + kc;
        const __nv_bfloat16* bg = bs + (size_t)(bn * 256 + tid) * DIM + kc;
        uint32_t sa = sa_base + buf * ABUF;
        uint32_t sbb = sb_base + buf * BBUF;
#pragma unroll
        for (int i = 0; i < 2; i++) {
            int seg = lsegA + i;
            cp_async16(sa + SWZ64(lrowA * 64 + seg * 16), ag + seg * 8);
        }
#pragma unroll
        for (int i = 0; i < 4; i++) {
            cp_async16(sbb + SWZ64(tid * 64 + i * 16), bg + i * 8);
        }
        asm volatile("cp.async.commit_group;" ::: "memory");
    };

    float acc[4][8][4];
#pragma unroll
    for (int mt = 0; mt < 4; mt++)
#pragma unroll
        for (int nt = 0; nt < 8; nt++)
#pragma unroll
            for (int i = 0; i < 4; i++) acc[mt][nt][i] = 0.0f;

    issue_chunk(0, 0);

    for (int c = 0; c < NCHUNK; c++) {
        if (c + 1 < NCHUNK) {
            issue_chunk(c + 1, (c + 1) & 1);
            asm volatile("cp.async.wait_group 1;" ::: "memory");
        } else {
            asm volatile("cp.async.wait_group 0;" ::: "memory");
        }
        __syncthreads();

        uint32_t sa = sa_base + (c & 1) * ABUF;
        uint32_t sbb = sb_base + (c & 1) * BBUF;
#pragma unroll
        for (int ks = 0; ks < 2; ks++) {
            uint32_t a[4][4];
#pragma unroll
            for (int mt = 0; mt < 4; mt++)
                ldsm_x4(a[mt][0], a[mt][1], a[mt][2], a[mt][3], sa + offA[mt][ks]);
            uint32_t b[4][4];
#pragma unroll
            for (int nt2 = 0; nt2 < 4; nt2++)
                ldsm_x4(b[nt2][0], b[nt2][1], b[nt2][2], b[nt2][3], sbb + offB[nt2][ks]);
#pragma unroll
            for (int mt = 0; mt < 4; mt++) {
#pragma unroll
                for (int nt = 0; nt < 8; nt++) {
                    const uint32_t* bb = b[nt >> 1];
                    int h = (nt & 1) * 2;
                    mma16816(acc[mt][nt], a[mt][0], a[mt][1], a[mt][2], a[mt][3],
                             bb[h], bb[h + 1]);
                }
            }
        }
        __syncthreads();
    }

    // --- epilogue: score/exp on fragments, row sums, sector-aligned stores ---
    // kk values (same for all mt): 8 nt x 2 cols
    float kkv[16];
#pragma unroll
    for (int nt = 0; nt < 8; nt++) {
        int gc = bn * 256 + warp_n * 64 + nt * 8 + (lane & 3) * 2;
        kkv[nt * 2]     = __ldg(&g_kk[gc]);
        kkv[nt * 2 + 1] = __ldg(&g_kk[gc + 1]);
    }

#pragma unroll
    for (int mt = 0; mt < 4; mt++) {
        int gr0 = bm * 128 + warp_m * 64 + mt * 16 + (lane >> 2);
        float qq0 = __ldg(&g_qq[gr0]);
        float qq1 = __ldg(&g_qq[gr0 + 8]);
        float s0 = 0.0f, s1 = 0.0f;
        size_t r0base = (size_t)gr0 * NK + bn * 256 + warp_n * 64;
#pragma unroll
        for (int nt = 0; nt < 8; nt++) {
            int lcol = nt * 8 + (lane & 3) * 2;
            float kk0 = kkv[nt * 2];
            float kk1 = kkv[nt * 2 + 1];
            float* aa = acc[mt][nt];
            float e00 = score_exp(aa[0], qq0, kk0);
            float e01 = score_exp(aa[1], qq0, kk1);
            float e10 = score_exp(aa[2], qq1, kk0);
            float e11 = score_exp(aa[3], qq1, kk1);
            s0 += e00 + e01;
            s1 += e10 + e11;
            *reinterpret_cast<float2*>(out + r0base + lcol)          = make_float2(e00, e01);
            *reinterpret_cast<float2*>(out + r0base + 8 * NK + lcol) = make_float2(e10, e11);
        }
        // quad reduce (lanes sharing a row differ in bits 0..1)
        s0 += __shfl_xor_sync(0xFFFFFFFFu, s0, 1);
        s0 += __shfl_xor_sync(0xFFFFFFFFu, s0, 2);
        s1 += __shfl_xor_sync(0xFFFFFFFFu, s1, 1);
        s1 += __shfl_xor_sync(0xFFFFFFFFu, s1, 2);
        if ((lane & 3) == 0) {
            atomicAdd(&g_rsum[gr0], s0);
            atomicAdd(&g_rsum[gr0 + 8], s1);
        }
    }
}

// ---------------------------------------------------------------------------
// Kernel 3: normalize in place. One block per row.
// ---------------------------------------------------------------------------
__global__ void __launch_bounds__(256)
normalize_kernel(float* __restrict__ out) {
    int row = blockIdx.x;
    float inv = 1.0f / g_rsum[row];
    float4* p = reinterpret_cast<float4*>(out + (size_t)row * NK);
    for (int i = threadIdx.x; i < NK / 4; i += blockDim.x) {
        float4 v = p[i];
        v.x *= inv; v.y *= inv; v.z *= inv; v.w *= inv;
        p[i] = v;
    }
}

// ---------------------------------------------------------------------------
extern "C" void kernel_launch(void* const* d_in, const int* in_sizes, int n_in,
                              void* d_out, int out_size) {
    const float* Q  = (const float*)d_in[0];
    const float* Kp = (const float*)d_in[1];
    float* out = (float*)d_out;

    // 1. sumsq + bf16 split + zero row sums
    prep_kernel<<<(2 * NQ) / 8, 256>>>(Q, Kp);

    // 2. tensor-core (mma.sync) GEMM + score/exp + row sums
    dim3 grid(NK / 256, NQ / 128);
    gemm_score_kernel<<<grid, 256>>>(out);

    // 3. normalize
    normalize_kernel<<<NQ, 256>>>(out);
}

// round 7
// speedup vs baseline: 1.4091x; 1.4091x over previous
#include <cuda_runtime.h>
#include <cuda_bf16.h>
#include <cstdint>
#include <math.h>

#define NQ 8192
#define NK 8192
#define DIM 512
#define CSCALE 0.01f
// exp(-0.5*(qd+kd)+55) = 2^(-0.5*log2e*(qd+kd) + 55*log2e)
#define NEG_HALF_LOG2E (-0.72134752044448170f)
#define SHIFT_LOG2E    (79.34822724889299f)

// ---------------------------------------------------------------------------
// Scratch (static device arrays; no runtime allocation)
// ---------------------------------------------------------------------------
__device__ __nv_bfloat16 g_qh[NQ * DIM];
__device__ __nv_bfloat16 g_ql[NQ * DIM];
__device__ __nv_bfloat16 g_kh[NK * DIM];
__device__ __nv_bfloat16 g_kl[NK * DIM];
__device__ float g_qq[NQ];
__device__ float g_kk[NK];
__device__ float g_rsum[NQ];

// ---------------------------------------------------------------------------
// helpers
// ---------------------------------------------------------------------------
__device__ __forceinline__ uint32_t smem_u32(const void* p) {
    uint32_t a;
    asm("{ .reg .u64 t; cvta.to.shared.u64 t, %1; cvt.u32.u64 %0, t; }" : "=r"(a) : "l"(p));
    return a;
}

// SW64 swizzle for 64-byte rows: XOR bits[5:4] with bits[8:7]
#define SWZ64(off) ((off) ^ (((off) >> 3) & 0x30))

__device__ __forceinline__ void cp_async16(uint32_t dst, const void* src) {
    asm volatile("cp.async.cg.shared.global [%0], [%1], 16;" :: "r"(dst), "l"(src));
}

__device__ __forceinline__ void ldsm_x4(uint32_t& r0, uint32_t& r1, uint32_t& r2, uint32_t& r3,
                                        uint32_t addr) {
    asm volatile("ldmatrix.sync.aligned.m8n8.x4.shared.b16 {%0,%1,%2,%3}, [%4];"
                 : "=r"(r0), "=r"(r1), "=r"(r2), "=r"(r3) : "r"(addr));
}

__device__ __forceinline__ void mma16816(float* c, uint32_t a0, uint32_t a1, uint32_t a2,
                                         uint32_t a3, uint32_t b0, uint32_t b1) {
    asm volatile(
        "mma.sync.aligned.m16n8k16.row.col.f32.bf16.bf16.f32 "
        "{%0,%1,%2,%3}, {%4,%5,%6,%7}, {%8,%9}, {%0,%1,%2,%3};"
        : "+f"(c[0]), "+f"(c[1]), "+f"(c[2]), "+f"(c[3])
        : "r"(a0), "r"(a1), "r"(a2), "r"(a3), "r"(b0), "r"(b1));
}

__device__ __forceinline__ float fsqrt_approx(float x) {
    float r; asm("sqrt.approx.f32 %0, %1;" : "=f"(r) : "f"(x)); return r;
}
__device__ __forceinline__ float fexp2_approx(float x) {
    float r; asm("ex2.approx.f32 %0, %1;" : "=f"(r) : "f"(x)); return r;
}

// exp(score + 55) with fixed shift (softmax-invariant; scores always << 0)
__device__ __forceinline__ float score_exp(float qk, float qq, float kk) {
    float norm2 = fmaxf(qq + kk - 2.0f * qk, 0.0f);
    float qdot  = qq - qk;
    float kdot  = qk - kk;
    float qd = fsqrt_approx(fmaf(CSCALE * qdot, qdot, norm2));
    float kd = fsqrt_approx(fmaf(CSCALE * kdot, kdot, norm2));
    return fexp2_approx(fmaf(NEG_HALF_LOG2E, qd + kd, SHIFT_LOG2E));
}

// ---------------------------------------------------------------------------
// Kernel 1: per-row sumsq + bf16 hi/lo split. One warp per row. Zeroes g_rsum.
// ---------------------------------------------------------------------------
__global__ void __launch_bounds__(256)
prep_kernel(const float* __restrict__ Q, const float* __restrict__ Kp) {
    int gw   = (blockIdx.x * blockDim.x + threadIdx.x) >> 5;
    int lane = threadIdx.x & 31;
    bool isQ = gw < NQ;
    int row  = isQ ? gw : gw - NQ;
    const float4* src = reinterpret_cast<const float4*>((isQ ? Q : Kp) + (size_t)row * DIM);
    __nv_bfloat16* hi = isQ ? g_qh : g_kh;
    __nv_bfloat16* lo = isQ ? g_ql : g_kl;

    float s = 0.0f;
#pragma unroll
    for (int i = 0; i < DIM / 128; i++) {
        float4 v = src[i * 32 + lane];
        s = fmaf(v.x, v.x, s); s = fmaf(v.y, v.y, s);
        s = fmaf(v.z, v.z, s); s = fmaf(v.w, v.w, s);

        __nv_bfloat16 h0 = __float2bfloat16(v.x);
        __nv_bfloat16 h1 = __float2bfloat16(v.y);
        __nv_bfloat16 h2 = __float2bfloat16(v.z);
        __nv_bfloat16 h3 = __float2bfloat16(v.w);
        __nv_bfloat16 l0 = __float2bfloat16(v.x - __bfloat162float(h0));
        __nv_bfloat16 l1 = __float2bfloat16(v.y - __bfloat162float(h1));
        __nv_bfloat16 l2 = __float2bfloat16(v.z - __bfloat162float(h2));
        __nv_bfloat16 l3 = __float2bfloat16(v.w - __bfloat162float(h3));

        int col = (i * 32 + lane) * 4;
        __nv_bfloat162 h01 = __nv_bfloat162(h0, h1);
        __nv_bfloat162 h23 = __nv_bfloat162(h2, h3);
        __nv_bfloat162 l01 = __nv_bfloat162(l0, l1);
        __nv_bfloat162 l23 = __nv_bfloat162(l2, l3);
        uint2 hu = make_uint2(*reinterpret_cast<uint32_t*>(&h01), *reinterpret_cast<uint32_t*>(&h23));
        uint2 lu = make_uint2(*reinterpret_cast<uint32_t*>(&l01), *reinterpret_cast<uint32_t*>(&l23));
        *reinterpret_cast<uint2*>(hi + (size_t)row * DIM + col) = hu;
        *reinterpret_cast<uint2*>(lo + (size_t)row * DIM + col) = lu;
    }
#pragma unroll
    for (int off = 16; off; off >>= 1) s += __shfl_xor_sync(0xFFFFFFFFu, s, off);
    if (lane == 0) {
        if (isQ) { g_qq[row] = s; g_rsum[row] = 0.0f; }
        else     { g_kk[row] = s; }
    }
}

// ---------------------------------------------------------------------------
// Kernel 2: mma.sync bf16 split GEMM (K_eff=1536) + fused score/exp epilogue.
// CTA tile 128x128, 8 warps (2x4), warptile 64x32, K-chunk 32.
// 3-stage cp.async pipeline, ONE barrier per chunk. smem = 3 x 16KB = 48KB.
// ---------------------------------------------------------------------------
#define NCHUNK 48
#define CK 32
#define BUFB 8192   // 128 rows x 64 bytes
#define STAGES 3

__global__ void __launch_bounds__(256, 2)
gemm_score_kernel(float* __restrict__ out) {
    __shared__ __align__(128) uint8_t sA[STAGES * BUFB];
    __shared__ __align__(128) uint8_t sB[STAGES * BUFB];

    const int tid  = threadIdx.x;
    const int wid  = tid >> 5;
    const int lane = tid & 31;
    const int bm = blockIdx.y;
    const int bn = blockIdx.x;
    const int warp_m = wid & 1;     // 0..1 -> 64-row half
    const int warp_n = wid >> 1;    // 0..3 -> 32-col quarter

    const uint32_t sa_base = smem_u32(sA);
    const uint32_t sb_base = smem_u32(sB);

    // --- precompute per-lane ldmatrix byte offsets (within a buffer) ---
    uint32_t offA[4][2], offB[2][2];
#pragma unroll
    for (int mt = 0; mt < 4; mt++) {
        int m = warp_m * 64 + mt * 16 + (lane & 15);
#pragma unroll
        for (int ks = 0; ks < 2; ks++) {
            int o = m * 64 + ks * 32 + (lane >> 4) * 16;
            offA[mt][ks] = SWZ64(o);
        }
    }
#pragma unroll
    for (int nt2 = 0; nt2 < 2; nt2++) {
        int n = warp_n * 32 + nt2 * 16 + (lane & 7) + ((lane >> 4) & 1) * 8;
#pragma unroll
        for (int ks = 0; ks < 2; ks++) {
            int o = n * 64 + ks * 32 + ((lane >> 3) & 1) * 16;
            offB[nt2][ks] = SWZ64(o);
        }
    }

    // loader: per chunk each thread moves 2 x 16B for A and for B
    const int lrow = tid >> 1;            // 0..127 (2 threads per 64B row)
    const int lseg = (tid & 1) * 2;       // segment pairs {0,1} or {2,3}

    auto issue_chunk = [&](int c, int buf) {
        const __nv_bfloat16 *as, *bs;
        if (c < 16)      { as = g_qh; bs = g_kh; }
        else if (c < 32) { as = g_qh; bs = g_kl; }
        else             { as = g_ql; bs = g_kh; }
        int kc = (c & 15) * CK;
        const __nv_bfloat16* ag = as + (size_t)(bm * 128 + lrow) * DIM + kc;
        const __nv_bfloat16* bg = bs + (size_t)(bn * 128 + lrow) * DIM + kc;
        uint32_t sa = sa_base + buf * BUFB;
        uint32_t sbb = sb_base + buf * BUFB;
#pragma unroll
        for (int i = 0; i < 2; i++) {
            int seg = lseg + i;                       // 16B segment 0..3
            uint32_t off = SWZ64(lrow * 64 + seg * 16);
            cp_async16(sa  + off, ag + seg * 8);
            cp_async16(sbb + off, bg + seg * 8);
        }
        asm volatile("cp.async.commit_group;" ::: "memory");
    };

    float acc[4][4][4];
#pragma unroll
    for (int mt = 0; mt < 4; mt++)
#pragma unroll
        for (int nt = 0; nt < 4; nt++)
#pragma unroll
            for (int i = 0; i < 4; i++) acc[mt][nt][i] = 0.0f;

    // prologue: fill stages 0 and 1
    issue_chunk(0, 0);
    issue_chunk(1, 1);

    int buf = 0;
    for (int c = 0; c < NCHUNK; c++) {
        if (c + 2 < NCHUNK) {
            asm volatile("cp.async.wait_group 1;" ::: "memory");
        } else {
            asm volatile("cp.async.wait_group 0;" ::: "memory");
        }
        __syncthreads();

        // issue next chunk AFTER the barrier: its target buffer (c+2)%3 ==
        // (c-1)%3 whose readers all completed before this barrier.
        if (c + 2 < NCHUNK) {
            int nb = buf + 2; if (nb >= STAGES) nb -= STAGES;
            issue_chunk(c + 2, nb);
        }

        uint32_t sa = sa_base + buf * BUFB;
        uint32_t sbb = sb_base + buf * BUFB;
#pragma unroll
        for (int ks = 0; ks < 2; ks++) {
            uint32_t a[4][4];
#pragma unroll
            for (int mt = 0; mt < 4; mt++)
                ldsm_x4(a[mt][0], a[mt][1], a[mt][2], a[mt][3], sa + offA[mt][ks]);
            uint32_t b[2][4];
#pragma unroll
            for (int nt2 = 0; nt2 < 2; nt2++)
                ldsm_x4(b[nt2][0], b[nt2][1], b[nt2][2], b[nt2][3], sbb + offB[nt2][ks]);
#pragma unroll
            for (int mt = 0; mt < 4; mt++) {
#pragma unroll
                for (int nt = 0; nt < 4; nt++) {
                    const uint32_t* bb = b[nt >> 1];
                    int h = (nt & 1) * 2;
                    mma16816(acc[mt][nt], a[mt][0], a[mt][1], a[mt][2], a[mt][3],
                             bb[h], bb[h + 1]);
                }
            }
        }
        buf++; if (buf >= STAGES) buf -= STAGES;
    }

    // --- epilogue: score/exp on fragments, row sums, sector-aligned stores ---
    float kkv[8];
#pragma unroll
    for (int nt = 0; nt < 4; nt++) {
        int gc = bn * 128 + warp_n * 32 + nt * 8 + (lane & 3) * 2;
        kkv[nt * 2]     = __ldg(&g_kk[gc]);
        kkv[nt * 2 + 1] = __ldg(&g_kk[gc + 1]);
    }

#pragma unroll
    for (int mt = 0; mt < 4; mt++) {
        int gr0 = bm * 128 + warp_m * 64 + mt * 16 + (lane >> 2);
        float qq0 = __ldg(&g_qq[gr0]);
        float qq1 = __ldg(&g_qq[gr0 + 8]);
        float s0 = 0.0f, s1 = 0.0f;
        size_t r0base = (size_t)gr0 * NK + bn * 128 + warp_n * 32;
#pragma unroll
        for (int nt = 0; nt < 4; nt++) {
            int lcol = nt * 8 + (lane & 3) * 2;
            float kk0 = kkv[nt * 2];
            float kk1 = kkv[nt * 2 + 1];
            float* aa = acc[mt][nt];
            float e00 = score_exp(aa[0], qq0, kk0);
            float e01 = score_exp(aa[1], qq0, kk1);
            float e10 = score_exp(aa[2], qq1, kk0);
            float e11 = score_exp(aa[3], qq1, kk1);
            s0 += e00 + e01;
            s1 += e10 + e11;
            *reinterpret_cast<float2*>(out + r0base + lcol)          = make_float2(e00, e01);
            *reinterpret_cast<float2*>(out + r0base + 8 * NK + lcol) = make_float2(e10, e11);
        }
        // quad reduce (lanes sharing a row differ in bits 0..1)
        s0 += __shfl_xor_sync(0xFFFFFFFFu, s0, 1);
        s0 += __shfl_xor_sync(0xFFFFFFFFu, s0, 2);
        s1 += __shfl_xor_sync(0xFFFFFFFFu, s1, 1);
        s1 += __shfl_xor_sync(0xFFFFFFFFu, s1, 2);
        if ((lane & 3) == 0) {
            atomicAdd(&g_rsum[gr0], s0);
            atomicAdd(&g_rsum[gr0 + 8], s1);
        }
    }
}

// ---------------------------------------------------------------------------
// Kernel 3: normalize in place. One block per row.
// ---------------------------------------------------------------------------
__global__ void __launch_bounds__(256)
normalize_kernel(float* __restrict__ out) {
    int row = blockIdx.x;
    float inv = 1.0f / g_rsum[row];
    float4* p = reinterpret_cast<float4*>(out + (size_t)row * NK);
    for (int i = threadIdx.x; i < NK / 4; i += blockDim.x) {
        float4 v = p[i];
        v.x *= inv; v.y *= inv; v.z *= inv; v.w *= inv;
        p[i] = v;
    }
}

// ---------------------------------------------------------------------------
extern "C" void kernel_launch(void* const* d_in, const int* in_sizes, int n_in,
                              void* d_out, int out_size) {
    const float* Q  = (const float*)d_in[0];
    const float* Kp = (const float*)d_in[1];
    float* out = (float*)d_out;

    // 1. sumsq + bf16 split + zero row sums
    prep_kernel<<<(2 * NQ) / 8, 256>>>(Q, Kp);

    // 2. tensor-core (mma.sync) GEMM + score/exp + row sums
    dim3 grid(NK / 128, NQ / 128);
    gemm_score_kernel<<<grid, 256>>>(out);

    // 3. normalize
    normalize_kernel<<<NQ, 256>>>(out);
}

// round 8
// speedup vs baseline: 1.4236x; 1.0103x over previous
#include <cuda_runtime.h>
#include <cuda_bf16.h>
#include <cstdint>
#include <math.h>

#define NQ 8192
#define NK 8192
#define DIM 512
#define CSCALE 0.01f
// exp(-0.5*(qd+kd)+55) = 2^(-0.5*log2e*(qd+kd) + 55*log2e)
#define NEG_HALF_LOG2E (-0.72134752044448170f)
#define SHIFT_LOG2E    (79.34822724889299f)

// ---------------------------------------------------------------------------
// Scratch (static device arrays; no runtime allocation)
// ---------------------------------------------------------------------------
__device__ __nv_bfloat16 g_qh[NQ * DIM];
__device__ __nv_bfloat16 g_ql[NQ * DIM];
__device__ __nv_bfloat16 g_kh[NK * DIM];
__device__ __nv_bfloat16 g_kl[NK * DIM];
__device__ float g_qq[NQ];
__device__ float g_kk[NK];
__device__ float g_rsum[NQ];

// ---------------------------------------------------------------------------
// helpers
// ---------------------------------------------------------------------------
__device__ __forceinline__ uint32_t smem_u32(const void* p) {
    uint32_t a;
    asm("{ .reg .u64 t; cvta.to.shared.u64 t, %1; cvt.u32.u64 %0, t; }" : "=r"(a) : "l"(p));
    return a;
}

// Full SW128 swizzle for 128-byte rows: bits[6:4] ^= bits[9:7] (3 row bits ->
// 8 distinct 16B positions -> conflict-free ldmatrix 8-row phases)
#define SWZ128(off) ((off) ^ (((off) >> 3) & 0x70))

__device__ __forceinline__ void cp_async16(uint32_t dst, const void* src) {
    asm volatile("cp.async.cg.shared.global [%0], [%1], 16;" :: "r"(dst), "l"(src));
}

__device__ __forceinline__ void ldsm_x4(uint32_t& r0, uint32_t& r1, uint32_t& r2, uint32_t& r3,
                                        uint32_t addr) {
    asm volatile("ldmatrix.sync.aligned.m8n8.x4.shared.b16 {%0,%1,%2,%3}, [%4];"
                 : "=r"(r0), "=r"(r1), "=r"(r2), "=r"(r3) : "r"(addr));
}

__device__ __forceinline__ void mma16816(float* c, uint32_t a0, uint32_t a1, uint32_t a2,
                                         uint32_t a3, uint32_t b0, uint32_t b1) {
    asm volatile(
        "mma.sync.aligned.m16n8k16.row.col.f32.bf16.bf16.f32 "
        "{%0,%1,%2,%3}, {%4,%5,%6,%7}, {%8,%9}, {%0,%1,%2,%3};"
        : "+f"(c[0]), "+f"(c[1]), "+f"(c[2]), "+f"(c[3])
        : "r"(a0), "r"(a1), "r"(a2), "r"(a3), "r"(b0), "r"(b1));
}

__device__ __forceinline__ float fsqrt_approx(float x) {
    float r; asm("sqrt.approx.f32 %0, %1;" : "=f"(r) : "f"(x)); return r;
}
__device__ __forceinline__ float fexp2_approx(float x) {
    float r; asm("ex2.approx.f32 %0, %1;" : "=f"(r) : "f"(x)); return r;
}

// exp(score + 55) with fixed shift (softmax-invariant; scores always << 0)
__device__ __forceinline__ float score_exp(float qk, float qq, float kk) {
    float norm2 = fmaxf(qq + kk - 2.0f * qk, 0.0f);
    float qdot  = qq - qk;
    float kdot  = qk - kk;
    float qd = fsqrt_approx(fmaf(CSCALE * qdot, qdot, norm2));
    float kd = fsqrt_approx(fmaf(CSCALE * kdot, kdot, norm2));
    return fexp2_approx(fmaf(NEG_HALF_LOG2E, qd + kd, SHIFT_LOG2E));
}

// ---------------------------------------------------------------------------
// Kernel 1: per-row sumsq + bf16 hi/lo split. One warp per row. Zeroes g_rsum.
// ---------------------------------------------------------------------------
__global__ void __launch_bounds__(256)
prep_kernel(const float* __restrict__ Q, const float* __restrict__ Kp) {
    int gw   = (blockIdx.x * blockDim.x + threadIdx.x) >> 5;
    int lane = threadIdx.x & 31;
    bool isQ = gw < NQ;
    int row  = isQ ? gw : gw - NQ;
    const float4* src = reinterpret_cast<const float4*>((isQ ? Q : Kp) + (size_t)row * DIM);
    __nv_bfloat16* hi = isQ ? g_qh : g_kh;
    __nv_bfloat16* lo = isQ ? g_ql : g_kl;

    float s = 0.0f;
#pragma unroll
    for (int i = 0; i < DIM / 128; i++) {
        float4 v = src[i * 32 + lane];
        s = fmaf(v.x, v.x, s); s = fmaf(v.y, v.y, s);
        s = fmaf(v.z, v.z, s); s = fmaf(v.w, v.w, s);

        __nv_bfloat16 h0 = __float2bfloat16(v.x);
        __nv_bfloat16 h1 = __float2bfloat16(v.y);
        __nv_bfloat16 h2 = __float2bfloat16(v.z);
        __nv_bfloat16 h3 = __float2bfloat16(v.w);
        __nv_bfloat16 l0 = __float2bfloat16(v.x - __bfloat162float(h0));
        __nv_bfloat16 l1 = __float2bfloat16(v.y - __bfloat162float(h1));
        __nv_bfloat16 l2 = __float2bfloat16(v.z - __bfloat162float(h2));
        __nv_bfloat16 l3 = __float2bfloat16(v.w - __bfloat162float(h3));

        int col = (i * 32 + lane) * 4;
        __nv_bfloat162 h01 = __nv_bfloat162(h0, h1);
        __nv_bfloat162 h23 = __nv_bfloat162(h2, h3);
        __nv_bfloat162 l01 = __nv_bfloat162(l0, l1);
        __nv_bfloat162 l23 = __nv_bfloat162(l2, l3);
        uint2 hu = make_uint2(*reinterpret_cast<uint32_t*>(&h01), *reinterpret_cast<uint32_t*>(&h23));
        uint2 lu = make_uint2(*reinterpret_cast<uint32_t*>(&l01), *reinterpret_cast<uint32_t*>(&l23));
        *reinterpret_cast<uint2*>(hi + (size_t)row * DIM + col) = hu;
        *reinterpret_cast<uint2*>(lo + (size_t)row * DIM + col) = lu;
    }
#pragma unroll
    for (int off = 16; off; off >>= 1) s += __shfl_xor_sync(0xFFFFFFFFu, s, off);
    if (lane == 0) {
        if (isQ) { g_qq[row] = s; g_rsum[row] = 0.0f; }
        else     { g_kk[row] = s; }
    }
}

// ---------------------------------------------------------------------------
// Kernel 2: mma.sync bf16 split GEMM (K_eff=1536) + fused score/exp epilogue.
// CTA tile 128x128, 8 warps (2x4), warptile 64x32, K-chunk 64, 128B rows with
// full SW128 swizzle (conflict-free ldsm). 3-stage pipeline, 96KB dynamic smem.
// ---------------------------------------------------------------------------
#define NCHUNK 24
#define CK 64
#define BUFB 16384    // 128 rows x 128 bytes
#define STAGES 3
#define DYN_SMEM (2 * STAGES * BUFB + 1024)

__global__ void __launch_bounds__(256, 2)
gemm_score_kernel(float* __restrict__ out) {
    extern __shared__ __align__(1024) uint8_t dyn_smem[];
    uint32_t sbase0 = smem_u32(dyn_smem);
    uint32_t sbase  = (sbase0 + 1023u) & ~1023u;
    const uint32_t sa_base = sbase;
    const uint32_t sb_base = sbase + STAGES * BUFB;

    const int tid  = threadIdx.x;
    const int wid  = tid >> 5;
    const int lane = tid & 31;
    const int bm = blockIdx.y;
    const int bn = blockIdx.x;
    const int warp_m = wid & 1;     // 0..1 -> 64-row half
    const int warp_n = wid >> 1;    // 0..3 -> 32-col quarter

    // --- precompute per-lane swizzled ldsm base offsets (ks=0) ---
    // addr(ks) = base ^ (ks << 5): k-byte bits (5,6) are disjoint from the
    // row/lane bits of base, and the swizzle mask depends only on row bits.
    uint32_t baseA[4], baseB[2];
#pragma unroll
    for (int mt = 0; mt < 4; mt++) {
        int m  = warp_m * 64 + mt * 16 + (lane & 15);
        int lo = (lane >> 4) * 16;
        baseA[mt] = (uint32_t)(m * 128 + lo) ^ (uint32_t)((m & 7) * 16);
    }
#pragma unroll
    for (int nt2 = 0; nt2 < 2; nt2++) {
        int n  = warp_n * 32 + nt2 * 16 + (lane & 7) + ((lane >> 4) & 1) * 8;
        int lo = ((lane >> 3) & 1) * 16;
        baseB[nt2] = (uint32_t)(n * 128 + lo) ^ (uint32_t)((n & 7) * 16);
    }

    // loader: 128 rows x 8 segs of 16B = 1024 segs per tile; 4 per thread
    const int lrow = tid >> 1;            // 0..127
    const int lseg = (tid & 1) * 4;       // segs {0..3} or {4..7}

    auto issue_chunk = [&](int c, int buf) {
        const __nv_bfloat16 *as, *bs;
        if (c < 8)       { as = g_qh; bs = g_kh; }
        else if (c < 16) { as = g_qh; bs = g_kl; }
        else             { as = g_ql; bs = g_kh; }
        int kc = (c & 7) * CK;
        const __nv_bfloat16* ag = as + (size_t)(bm * 128 + lrow) * DIM + kc;
        const __nv_bfloat16* bg = bs + (size_t)(bn * 128 + lrow) * DIM + kc;
        uint32_t sa  = sa_base + buf * BUFB;
        uint32_t sbb = sb_base + buf * BUFB;
#pragma unroll
        for (int i = 0; i < 4; i++) {
            int seg = lseg + i;
            uint32_t off = SWZ128(lrow * 128 + seg * 16);
            cp_async16(sa  + off, ag + seg * 8);
            cp_async16(sbb + off, bg + seg * 8);
        }
        asm volatile("cp.async.commit_group;" ::: "memory");
    };

    float acc[4][4][4];
#pragma unroll
    for (int mt = 0; mt < 4; mt++)
#pragma unroll
        for (int nt = 0; nt < 4; nt++)
#pragma unroll
            for (int i = 0; i < 4; i++) acc[mt][nt][i] = 0.0f;

    // prologue: fill stages 0 and 1
    issue_chunk(0, 0);
    issue_chunk(1, 1);

    int buf = 0;
    for (int c = 0; c < NCHUNK; c++) {
        if (c + 2 < NCHUNK) {
            asm volatile("cp.async.wait_group 1;" ::: "memory");
        } else {
            asm volatile("cp.async.wait_group 0;" ::: "memory");
        }
        __syncthreads();

        // issue next chunk AFTER the barrier: target buffer (c+2)%3 == (c-1)%3
        // whose readers all completed before this barrier.
        if (c + 2 < NCHUNK) {
            int nb = buf + 2; if (nb >= STAGES) nb -= STAGES;
            issue_chunk(c + 2, nb);
        }

        uint32_t sa  = sa_base + buf * BUFB;
        uint32_t sbb = sb_base + buf * BUFB;
#pragma unroll
        for (int ks = 0; ks < 4; ks++) {
            uint32_t kx = (uint32_t)(ks << 5);
            uint32_t a[4][4];
#pragma unroll
            for (int mt = 0; mt < 4; mt++)
                ldsm_x4(a[mt][0], a[mt][1], a[mt][2], a[mt][3], sa + (baseA[mt] ^ kx));
            uint32_t b[2][4];
#pragma unroll
            for (int nt2 = 0; nt2 < 2; nt2++)
                ldsm_x4(b[nt2][0], b[nt2][1], b[nt2][2], b[nt2][3], sbb + (baseB[nt2] ^ kx));
#pragma unroll
            for (int mt = 0; mt < 4; mt++) {
#pragma unroll
                for (int nt = 0; nt < 4; nt++) {
                    const uint32_t* bb = b[nt >> 1];
                    int h = (nt & 1) * 2;
                    mma16816(acc[mt][nt], a[mt][0], a[mt][1], a[mt][2], a[mt][3],
                             bb[h], bb[h + 1]);
                }
            }
        }
        buf++; if (buf >= STAGES) buf -= STAGES;
    }

    // --- epilogue: score/exp on fragments, row sums, sector-aligned stores ---
    float kkv[8];
#pragma unroll
    for (int nt = 0; nt < 4; nt++) {
        int gc = bn * 128 + warp_n * 32 + nt * 8 + (lane & 3) * 2;
        kkv[nt * 2]     = __ldg(&g_kk[gc]);
        kkv[nt * 2 + 1] = __ldg(&g_kk[gc + 1]);
    }

#pragma unroll
    for (int mt = 0; mt < 4; mt++) {
        int gr0 = bm * 128 + warp_m * 64 + mt * 16 + (lane >> 2);
        float qq0 = __ldg(&g_qq[gr0]);
        float qq1 = __ldg(&g_qq[gr0 + 8]);
        float s0 = 0.0f, s1 = 0.0f;
        size_t r0base = (size_t)gr0 * NK + bn * 128 + warp_n * 32;
#pragma unroll
        for (int nt = 0; nt < 4; nt++) {
            int lcol = nt * 8 + (lane & 3) * 2;
            float kk0 = kkv[nt * 2];
            float kk1 = kkv[nt * 2 + 1];
            float* aa = acc[mt][nt];
            float e00 = score_exp(aa[0], qq0, kk0);
            float e01 = score_exp(aa[1], qq0, kk1);
            float e10 = score_exp(aa[2], qq1, kk0);
            float e11 = score_exp(aa[3], qq1, kk1);
            s0 += e00 + e01;
            s1 += e10 + e11;
            *reinterpret_cast<float2*>(out + r0base + lcol)          = make_float2(e00, e01);
            *reinterpret_cast<float2*>(out + r0base + 8 * NK + lcol) = make_float2(e10, e11);
        }
        // quad reduce (lanes sharing a row differ in bits 0..1)
        s0 += __shfl_xor_sync(0xFFFFFFFFu, s0, 1);
        s0 += __shfl_xor_sync(0xFFFFFFFFu, s0, 2);
        s1 += __shfl_xor_sync(0xFFFFFFFFu, s1, 1);
        s1 += __shfl_xor_sync(0xFFFFFFFFu, s1, 2);
        if ((lane & 3) == 0) {
            atomicAdd(&g_rsum[gr0], s0);
            atomicAdd(&g_rsum[gr0 + 8], s1);
        }
    }
}

// ---------------------------------------------------------------------------
// Kernel 3: normalize in place. One block per row.
// ---------------------------------------------------------------------------
__global__ void __launch_bounds__(256)
normalize_kernel(float* __restrict__ out) {
    int row = blockIdx.x;
    float inv = 1.0f / g_rsum[row];
    float4* p = reinterpret_cast<float4*>(out + (size_t)row * NK);
    for (int i = threadIdx.x; i < NK / 4; i += blockDim.x) {
        float4 v = p[i];
        v.x *= inv; v.y *= inv; v.z *= inv; v.w *= inv;
        p[i] = v;
    }
}

// ---------------------------------------------------------------------------
extern "C" void kernel_launch(void* const* d_in, const int* in_sizes, int n_in,
                              void* d_out, int out_size) {
    const float* Q  = (const float*)d_in[0];
    const float* Kp = (const float*)d_in[1];
    float* out = (float*)d_out;

    // opt-in smem (non-stream op, idempotent, capture-safe)
    cudaFuncSetAttribute(gemm_score_kernel,
                         cudaFuncAttributeMaxDynamicSharedMemorySize, DYN_SMEM);

    // 1. sumsq + bf16 split + zero row sums
    prep_kernel<<<(2 * NQ) / 8, 256>>>(Q, Kp);

    // 2. tensor-core (mma.sync) GEMM + score/exp + row sums
    dim3 grid(NK / 128, NQ / 128);
    gemm_score_kernel<<<grid, 256, DYN_SMEM>>>(out);

    // 3. normalize
    normalize_kernel<<<NQ, 256>>>(out);
}

// round 10
// speedup vs baseline: 1.4339x; 1.0073x over previous
#include <cuda_runtime.h>
#include <cuda_bf16.h>
#include <cuda_fp8.h>
#include <cstdint>
#include <math.h>

#define NQ 8192
#define NK 8192
#define DIM 512
#define CSCALE 0.01f
#define NEG_HALF_LOG2E (-0.72134752044448170f)
#define SHIFT_LOG2E    (79.34822724889299f)
#define CSCALE_INV512  (1.0f / 512.0f)

// ---------------------------------------------------------------------------
// Scratch
// ---------------------------------------------------------------------------
__device__ __nv_bfloat16 g_qh[NQ * DIM];
__device__ __nv_bfloat16 g_kh[NK * DIM];
__device__ uint8_t g_q8 [NQ * DIM];   // e4m3(q)
__device__ uint8_t g_ql8[NQ * DIM];   // e4m3(512*(q - bf16(q)))
__device__ uint8_t g_k8 [NK * DIM];   // e4m3(k)
__device__ uint8_t g_kl8[NK * DIM];   // e4m3(512*(k - bf16(k)))
__device__ float g_qq[NQ];
__device__ float g_kk[NK];
__device__ float g_rsum[NQ];

// ---------------------------------------------------------------------------
// helpers
// ---------------------------------------------------------------------------
__device__ __forceinline__ uint32_t smem_u32(const void* p) {
    uint32_t a;
    asm("{ .reg .u64 t; cvta.to.shared.u64 t, %1; cvt.u32.u64 %0, t; }" : "=r"(a) : "l"(p));
    return a;
}

#define SWZ128(off) ((off) ^ (((off) >> 3) & 0x70))
#define SWZ64(off)  ((off) ^ (((off) >> 3) & 0x30))

__device__ __forceinline__ void cp_async16(uint32_t dst, const void* src) {
    asm volatile("cp.async.cg.shared.global [%0], [%1], 16;" :: "r"(dst), "l"(src));
}

__device__ __forceinline__ void ldsm_x4(uint32_t& r0, uint32_t& r1, uint32_t& r2, uint32_t& r3,
                                        uint32_t addr) {
    asm volatile("ldmatrix.sync.aligned.m8n8.x4.shared.b16 {%0,%1,%2,%3}, [%4];"
                 : "=r"(r0), "=r"(r1), "=r"(r2), "=r"(r3) : "r"(addr));
}

__device__ __forceinline__ void mma16816(float* c, uint32_t a0, uint32_t a1, uint32_t a2,
                                         uint32_t a3, uint32_t b0, uint32_t b1) {
    asm volatile(
        "mma.sync.aligned.m16n8k16.row.col.f32.bf16.bf16.f32 "
        "{%0,%1,%2,%3}, {%4,%5,%6,%7}, {%8,%9}, {%0,%1,%2,%3};"
        : "+f"(c[0]), "+f"(c[1]), "+f"(c[2]), "+f"(c[3])
        : "r"(a0), "r"(a1), "r"(a2), "r"(a3), "r"(b0), "r"(b1));
}

__device__ __forceinline__ void mma16832_fp8(float* c, uint32_t a0, uint32_t a1, uint32_t a2,
                                             uint32_t a3, uint32_t b0, uint32_t b1) {
    asm volatile(
        "mma.sync.aligned.m16n8k32.row.col.f32.e4m3.e4m3.f32 "
        "{%0,%1,%2,%3}, {%4,%5,%6,%7}, {%8,%9}, {%0,%1,%2,%3};"
        : "+f"(c[0]), "+f"(c[1]), "+f"(c[2]), "+f"(c[3])
        : "r"(a0), "r"(a1), "r"(a2), "r"(a3), "r"(b0), "r"(b1));
}

__device__ __forceinline__ float fsqrt_approx(float x) {
    float r; asm("sqrt.approx.f32 %0, %1;" : "=f"(r) : "f"(x)); return r;
}
__device__ __forceinline__ float fexp2_approx(float x) {
    float r; asm("ex2.approx.f32 %0, %1;" : "=f"(r) : "f"(x)); return r;
}

__device__ __forceinline__ float score_exp(float qk, float qq, float kk) {
    float norm2 = fmaxf(qq + kk - 2.0f * qk, 0.0f);
    float qdot  = qq - qk;
    float kdot  = qk - kk;
    float qd = fsqrt_approx(fmaf(CSCALE * qdot, qdot, norm2));
    float kd = fsqrt_approx(fmaf(CSCALE * kdot, kdot, norm2));
    return fexp2_approx(fmaf(NEG_HALF_LOG2E, qd + kd, SHIFT_LOG2E));
}

__device__ __forceinline__ uint8_t to_e4m3(float f) {
    return (uint8_t)__nv_cvt_float_to_fp8(f, __NV_SATFINITE, __NV_E4M3);
}

// ---------------------------------------------------------------------------
// Kernel 1: per-row sumsq + bf16-hi + fp8 splits. One warp per row.
// ---------------------------------------------------------------------------
__global__ void __launch_bounds__(256)
prep_kernel(const float* __restrict__ Q, const float* __restrict__ Kp) {
    int gw   = (blockIdx.x * blockDim.x + threadIdx.x) >> 5;
    int lane = threadIdx.x & 31;
    bool isQ = gw < NQ;
    int row  = isQ ? gw : gw - NQ;
    const float4* src = reinterpret_cast<const float4*>((isQ ? Q : Kp) + (size_t)row * DIM);
    __nv_bfloat16* hi = isQ ? g_qh : g_kh;
    uint8_t* f8  = isQ ? g_q8  : g_k8;
    uint8_t* l8  = isQ ? g_ql8 : g_kl8;

    float s = 0.0f;
#pragma unroll
    for (int i = 0; i < DIM / 128; i++) {
        float4 v = src[i * 32 + lane];
        s = fmaf(v.x, v.x, s); s = fmaf(v.y, v.y, s);
        s = fmaf(v.z, v.z, s); s = fmaf(v.w, v.w, s);

        __nv_bfloat16 h0 = __float2bfloat16(v.x);
        __nv_bfloat16 h1 = __float2bfloat16(v.y);
        __nv_bfloat16 h2 = __float2bfloat16(v.z);
        __nv_bfloat16 h3 = __float2bfloat16(v.w);

        uint32_t p8 = (uint32_t)to_e4m3(v.x) | ((uint32_t)to_e4m3(v.y) << 8) |
                      ((uint32_t)to_e4m3(v.z) << 16) | ((uint32_t)to_e4m3(v.w) << 24);
        uint32_t pl8 =
            (uint32_t)to_e4m3(512.0f * (v.x - __bfloat162float(h0))) |
            ((uint32_t)to_e4m3(512.0f * (v.y - __bfloat162float(h1))) << 8) |
            ((uint32_t)to_e4m3(512.0f * (v.z - __bfloat162float(h2))) << 16) |
            ((uint32_t)to_e4m3(512.0f * (v.w - __bfloat162float(h3))) << 24);

        int col = (i * 32 + lane) * 4;
        __nv_bfloat162 h01 = __nv_bfloat162(h0, h1);
        __nv_bfloat162 h23 = __nv_bfloat162(h2, h3);
        uint2 hu = make_uint2(*reinterpret_cast<uint32_t*>(&h01), *reinterpret_cast<uint32_t*>(&h23));
        *reinterpret_cast<uint2*>(hi + (size_t)row * DIM + col) = hu;
        reinterpret_cast<uint32_t*>(f8 + (size_t)row * DIM)[col >> 2] = p8;
        reinterpret_cast<uint32_t*>(l8 + (size_t)row * DIM)[col >> 2] = pl8;
    }
#pragma unroll
    for (int off = 16; off; off >>= 1) s += __shfl_xor_sync(0xFFFFFFFFu, s, off);
    if (lane == 0) {
        if (isQ) { g_qq[row] = s; g_rsum[row] = 0.0f; }
        else     { g_kk[row] = s; }
    }
}

// ---------------------------------------------------------------------------
// Kernel 2: mixed bf16/fp8 GEMM + fused score/exp epilogue.
// Chunks 0-7: fp8 corrections (q*kl + ql*k, scaled x512). Then acc /= 512.
// Chunks 8-15: bf16 qh*kh accumulated on top.
// CTA tile 128x128, 8 warps, warptile 64x32. 3-stage pipeline, 32KB stages.
// ---------------------------------------------------------------------------
#define NCHUNK 16
#define STAGE_B 32768
#define STAGES 3
#define DYN_SMEM (STAGES * STAGE_B + 1024)

__global__ void __launch_bounds__(256, 2)
gemm_score_kernel(float* __restrict__ out) {
    extern __shared__ __align__(1024) uint8_t dyn_smem[];
    uint32_t sbase0 = smem_u32(dyn_smem);
    uint32_t sbase  = (sbase0 + 1023u) & ~1023u;

    const int tid  = threadIdx.x;
    const int wid  = tid >> 5;
    const int lane = tid & 31;
    const int bm = blockIdx.y;
    const int bn = blockIdx.x;
    const int warp_m = wid & 1;
    const int warp_n = wid >> 1;

    // --- bf16 ldsm base offsets (128B rows, SW128) ---
    uint32_t baseA[4], baseB[2];
#pragma unroll
    for (int mt = 0; mt < 4; mt++) {
        int m  = warp_m * 64 + mt * 16 + (lane & 15);
        int lo = (lane >> 4) * 16;
        baseA[mt] = (uint32_t)(m * 128 + lo) ^ (uint32_t)((m & 7) * 16);
    }
#pragma unroll
    for (int nt2 = 0; nt2 < 2; nt2++) {
        int n  = warp_n * 32 + nt2 * 16 + (lane & 7) + ((lane >> 4) & 1) * 8;
        int lo = ((lane >> 3) & 1) * 16;
        baseB[nt2] = (uint32_t)(n * 128 + lo) ^ (uint32_t)((n & 7) * 16);
    }

    // --- fp8 ldsm base offsets (64B rows, SW64) ---
    // A frag m16k32: m0=rows0-7 half0, m1=rows8-15 half0, m2=rows0-7 half1, m3=rows8-15 half1
    uint32_t base8A[4], base8B[2];
#pragma unroll
    for (int mt = 0; mt < 4; mt++) {
        int r  = warp_m * 64 + mt * 16 + (lane & 7) + ((lane >> 3) & 1) * 8;
        int hf = (lane >> 4) * 16;
        base8A[mt] = SWZ64((uint32_t)(r * 64 + hf));
    }
    // B frag pair (2 x n8k32): m0/m1 = colsA half0/half1, m2/m3 = colsB half0/half1
#pragma unroll
    for (int p = 0; p < 2; p++) {
        int c  = warp_n * 32 + p * 16 + (lane & 7) + ((lane >> 4) & 1) * 8;
        int hf = ((lane >> 3) & 1) * 16;
        base8B[p] = SWZ64((uint32_t)(c * 64 + hf));
    }

    const int lrow = tid >> 1;
    const int lseg = (tid & 1) * 4;

    auto issue_chunk = [&](int c, int buf) {
        uint32_t stg = sbase + buf * STAGE_B;
        if (c < 8) {
            int kc = c * 64;
            // tiles: 0=q8(A), 1=ql8(A), 2=kl8(B), 3=k8(B); 8KB each
#pragma unroll
            for (int i = 0; i < 8; i++) {
                const int tile = i >> 1;
                int v   = (i & 1) * 256 + tid;    // 0..511 within tile
                int row = v >> 2;
                int seg = v & 3;
                const uint8_t* srcp;
                size_t goff;
                if (tile == 0)      { srcp = g_q8;  goff = (size_t)(bm * 128 + row) * DIM; }
                else if (tile == 1) { srcp = g_ql8; goff = (size_t)(bm * 128 + row) * DIM; }
                else if (tile == 2) { srcp = g_kl8; goff = (size_t)(bn * 128 + row) * DIM; }
                else                { srcp = g_k8;  goff = (size_t)(bn * 128 + row) * DIM; }
                cp_async16(stg + tile * 8192 + SWZ64(row * 64 + seg * 16),
                           srcp + goff + kc + seg * 16);
            }
        } else {
            int kc = (c - 8) * 64;
            const __nv_bfloat16* ag = g_qh + (size_t)(bm * 128 + lrow) * DIM + kc;
            const __nv_bfloat16* bg = g_kh + (size_t)(bn * 128 + lrow) * DIM + kc;
#pragma unroll
            for (int i = 0; i < 4; i++) {
                int seg = lseg + i;
                uint32_t off = SWZ128(lrow * 128 + seg * 16);
                cp_async16(stg + off,         ag + seg * 8);
                cp_async16(stg + 16384 + off, bg + seg * 8);
            }
        }
        asm volatile("cp.async.commit_group;" ::: "memory");
    };

    float acc[4][4][4];
#pragma unroll
    for (int mt = 0; mt < 4; mt++)
#pragma unroll
        for (int nt = 0; nt < 4; nt++)
#pragma unroll
            for (int i = 0; i < 4; i++) acc[mt][nt][i] = 0.0f;

    issue_chunk(0, 0);
    issue_chunk(1, 1);

    int buf = 0;
    for (int c = 0; c < NCHUNK; c++) {
        if (c + 2 < NCHUNK) {
            asm volatile("cp.async.wait_group 1;" ::: "memory");
        } else {
            asm volatile("cp.async.wait_group 0;" ::: "memory");
        }
        __syncthreads();

        if (c + 2 < NCHUNK) {
            int nb = buf + 2; if (nb >= STAGES) nb -= STAGES;
            issue_chunk(c + 2, nb);
        }

        uint32_t stg = sbase + buf * STAGE_B;
        if (c < 8) {
            // fp8 corrections: term1 q8*kl8, term2 ql8*k8
            uint32_t tA0 = stg;          // q8
            uint32_t tA1 = stg + 8192;   // ql8
            uint32_t tB0 = stg + 16384;  // kl8
            uint32_t tB1 = stg + 24576;  // k8
#pragma unroll
            for (int s = 0; s < 2; s++) {
                uint32_t kx = (uint32_t)(s << 5);
                uint32_t a[4][4], b[2][4];
#pragma unroll
                for (int mt = 0; mt < 4; mt++)
                    ldsm_x4(a[mt][0], a[mt][1], a[mt][2], a[mt][3], tA0 + (base8A[mt] ^ kx));
#pragma unroll
                for (int p = 0; p < 2; p++)
                    ldsm_x4(b[p][0], b[p][1], b[p][2], b[p][3], tB0 + (base8B[p] ^ kx));
#pragma unroll
                for (int mt = 0; mt < 4; mt++)
#pragma unroll
                    for (int nt = 0; nt < 4; nt++) {
                        const uint32_t* bb = b[nt >> 1];
                        int h = (nt & 1) * 2;
                        mma16832_fp8(acc[mt][nt], a[mt][0], a[mt][1], a[mt][2], a[mt][3],
                                     bb[h], bb[h + 1]);
                    }
#pragma unroll
                for (int mt = 0; mt < 4; mt++)
                    ldsm_x4(a[mt][0], a[mt][1], a[mt][2], a[mt][3], tA1 + (base8A[mt] ^ kx));
#pragma unroll
                for (int p = 0; p < 2; p++)
                    ldsm_x4(b[p][0], b[p][1], b[p][2], b[p][3], tB1 + (base8B[p] ^ kx));
#pragma unroll
                for (int mt = 0; mt < 4; mt++)
#pragma unroll
                    for (int nt = 0; nt < 4; nt++) {
                        const uint32_t* bb = b[nt >> 1];
                        int h = (nt & 1) * 2;
                        mma16832_fp8(acc[mt][nt], a[mt][0], a[mt][1], a[mt][2], a[mt][3],
                                     bb[h], bb[h + 1]);
                    }
            }
            if (c == 7) {
                // corrections were computed at x512 scale
#pragma unroll
                for (int mt = 0; mt < 4; mt++)
#pragma unroll
                    for (int nt = 0; nt < 4; nt++)
#pragma unroll
                        for (int i = 0; i < 4; i++) acc[mt][nt][i] *= CSCALE_INV512;
            }
        } else {
            uint32_t sa  = stg;
            uint32_t sbb = stg + 16384;
#pragma unroll
            for (int ks = 0; ks < 4; ks++) {
                uint32_t kx = (uint32_t)(ks << 5);
                uint32_t a[4][4], b[2][4];
#pragma unroll
                for (int mt = 0; mt < 4; mt++)
                    ldsm_x4(a[mt][0], a[mt][1], a[mt][2], a[mt][3], sa + (baseA[mt] ^ kx));
#pragma unroll
                for (int nt2 = 0; nt2 < 2; nt2++)
                    ldsm_x4(b[nt2][0], b[nt2][1], b[nt2][2], b[nt2][3], sbb + (baseB[nt2] ^ kx));
#pragma unroll
                for (int mt = 0; mt < 4; mt++)
#pragma unroll
                    for (int nt = 0; nt < 4; nt++) {
                        const uint32_t* bb = b[nt >> 1];
                        int h = (nt & 1) * 2;
                        mma16816(acc[mt][nt], a[mt][0], a[mt][1], a[mt][2], a[mt][3],
                                 bb[h], bb[h + 1]);
                    }
            }
        }
        buf++; if (buf >= STAGES) buf -= STAGES;
    }

    // --- epilogue ---
    float kkv[8];
#pragma unroll
    for (int nt = 0; nt < 4; nt++) {
        int gc = bn * 128 + warp_n * 32 + nt * 8 + (lane & 3) * 2;
        kkv[nt * 2]     = __ldg(&g_kk[gc]);
        kkv[nt * 2 + 1] = __ldg(&g_kk[gc + 1]);
    }

#pragma unroll
    for (int mt = 0; mt < 4; mt++) {
        int gr0 = bm * 128 + warp_m * 64 + mt * 16 + (lane >> 2);
        float qq0 = __ldg(&g_qq[gr0]);
        float qq1 = __ldg(&g_qq[gr0 + 8]);
        float s0 = 0.0f, s1 = 0.0f;
        size_t r0base = (size_t)gr0 * NK + bn * 128 + warp_n * 32;
#pragma unroll
        for (int nt = 0; nt < 4; nt++) {
            int lcol = nt * 8 + (lane & 3) * 2;
            float kk0 = kkv[nt * 2];
            float kk1 = kkv[nt * 2 + 1];
            float* aa = acc[mt][nt];
            float e00 = score_exp(aa[0], qq0, kk0);
            float e01 = score_exp(aa[1], qq0, kk1);
            float e10 = score_exp(aa[2], qq1, kk0);
            float e11 = score_exp(aa[3], qq1, kk1);
            s0 += e00 + e01;
            s1 += e10 + e11;
            *reinterpret_cast<float2*>(out + r0base + lcol)          = make_float2(e00, e01);
            *reinterpret_cast<float2*>(out + r0base + 8 * NK + lcol) = make_float2(e10, e11);
        }
        s0 += __shfl_xor_sync(0xFFFFFFFFu, s0, 1);
        s0 += __shfl_xor_sync(0xFFFFFFFFu, s0, 2);
        s1 += __shfl_xor_sync(0xFFFFFFFFu, s1, 1);
        s1 += __shfl_xor_sync(0xFFFFFFFFu, s1, 2);
        if ((lane & 3) == 0) {
            atomicAdd(&g_rsum[gr0], s0);
            atomicAdd(&g_rsum[gr0 + 8], s1);
        }
    }
}

// ---------------------------------------------------------------------------
// Kernel 3: normalize in place. One block per row.
// ---------------------------------------------------------------------------
__global__ void __launch_bounds__(256)
normalize_kernel(float* __restrict__ out) {
    int row = blockIdx.x;
    float inv = 1.0f / g_rsum[row];
    float4* p = reinterpret_cast<float4*>(out + (size_t)row * NK);
    for (int i = threadIdx.x; i < NK / 4; i += blockDim.x) {
        float4 v = p[i];
        v.x *= inv; v.y *= inv; v.z *= inv; v.w *= inv;
        p[i] = v;
    }
}

// ---------------------------------------------------------------------------
extern "C" void kernel_launch(void* const* d_in, const int* in_sizes, int n_in,
                              void* d_out, int out_size) {
    const float* Q  = (const float*)d_in[0];
    const float* Kp = (const float*)d_in[1];
    float* out = (float*)d_out;

    cudaFuncSetAttribute(gemm_score_kernel,
                         cudaFuncAttributeMaxDynamicSharedMemorySize, DYN_SMEM);

    prep_kernel<<<(2 * NQ) / 8, 256>>>(Q, Kp);

    dim3 grid(NK / 128, NQ / 128);
    gemm_score_kernel<<<grid, 256, DYN_SMEM>>>(out);

    normalize_kernel<<<NQ, 256>>>(out);
}